// round 14
// baseline (speedup 1.0000x reference)
#include <cuda_runtime.h>
#include <cuda_fp16.h>
#include <math.h>

#define N_POS   131072
#define KCODES  512
#define DDIM    64
#define GRID    1024             // 128 positions per CTA
#define NTHR    512
#define TAU     2.5e-4f

// ---- device scratch (no allocation allowed) ----
__device__ uint4  g_ef16[4608];    // fp16 [k][72]: cols 0-63 = -2e, 64 = eN, 65 = 1.0, 66-71 = 0
__device__ int    g_counts[KCODES];
__device__ double g_sse[GRID];
__device__ unsigned g_done;        // zero-init; self-resetting

// ---------- helpers ----------
static __device__ __forceinline__ void mma16816h(float& c0, float& c1, float& c2, float& c3,
                                                 unsigned a0, unsigned a1, unsigned a2, unsigned a3,
                                                 unsigned b0, unsigned b1) {
    asm volatile("mma.sync.aligned.m16n8k16.row.col.f32.f16.f16.f32 "
                 "{%0,%1,%2,%3}, {%4,%5,%6,%7}, {%8,%9}, {%0,%1,%2,%3};"
                 : "+f"(c0), "+f"(c1), "+f"(c2), "+f"(c3)
                 : "r"(a0), "r"(a1), "r"(a2), "r"(a3), "r"(b0), "r"(b1));
}
static __device__ __forceinline__ void mma16808h(float& c0, float& c1, float& c2, float& c3,
                                                 unsigned a0, unsigned a1, unsigned b0) {
    asm volatile("mma.sync.aligned.m16n8k8.row.col.f32.f16.f16.f32 "
                 "{%0,%1,%2,%3}, {%4,%5}, {%6}, {%0,%1,%2,%3};"
                 : "+f"(c0), "+f"(c1), "+f"(c2), "+f"(c3)
                 : "r"(a0), "r"(a1), "r"(b0));
}
#define LDSM4(d0, d1, d2, d3, addr)                                          \
    asm volatile("ldmatrix.sync.aligned.m8n8.x4.shared.b16 {%0,%1,%2,%3}, [%4];" \
                 : "=r"(d0), "=r"(d1), "=r"(d2), "=r"(d3) : "r"(addr))
#define LDSM2(d0, d1, addr)                                                  \
    asm volatile("ldmatrix.sync.aligned.m8n8.x2.shared.b16 {%0,%1}, [%2];"   \
                 : "=r"(d0), "=r"(d1) : "r"(addr))

static __device__ __forceinline__ unsigned smem_u32(const void* p) {
    unsigned a;
    asm("{ .reg .u64 t; cvta.to.shared.u64 t, %1; cvt.u32.u64 %0, t; }" : "=r"(a) : "l"(p));
    return a;
}
static __device__ __forceinline__ unsigned umn(unsigned a, unsigned b) { return a < b ? a : b; }
static __device__ __forceinline__ unsigned umx(unsigned a, unsigned b) { return a > b ? a : b; }
static __device__ __forceinline__ unsigned packscore(float s, int k) {
    return (__float_as_uint(s) & 0xFFFFFE00u) | (unsigned)k;
}

// ---------- smem layout (bytes), fixed regions: 94976 total ----------
#define SE_H   0                 // e fp16 [512][72] pitch 144B (dead after MMA -> overlay)
#define SZ_H   73728             // z fp16 [128][72]
#define SZSQP  92160             // float[512]
#define SZSQ   94208             // float[128]
#define S_WS   94720             // double[16]
#define S_WS2  94848             // double[16]
#define MAIN_SMEM 94976
// ---- overlays inside SE_H (valid only AFTER post-MMA syncthreads) ----
#define OV_BP    0               // uint[256] packed best
#define OV_SP    1024            // uint[256] packed sec
#define OV_HIST  2048            // int[512]
#define OV_ROWK  4096            // int[128]
#define OV_FBC   4608            // int
#define OV_FBR   4736            // int[128]
#define OV_FBK2  5248            // int[16]
#define OV_FBS2  5312            // float[16]
#define OV_FBK   5376            // int[8]
#define OV_FBSC  5408            // float[8]
#define OV_LAST  5440            // int
#define OV_FZS   8192            // float[8][64]
#define OV_FZQ   10240           // float[8]
#define OV_FSC   16384           // float[8][512]

// ===========================================================================
// Prep: codebook -> fp16 of -2e at pitch 72 + [eN, 1.0, 0..] in spare cols
// ===========================================================================
__global__ void prep_kernel(const float* __restrict__ e) {
    int t = blockIdx.x * blockDim.x + threadIdx.x;   // 64 x 512 = 32768
    int k = t >> 6, d = t & 63;
    ((__half*)g_ef16)[k * 72 + d] = __float2half_rn(-2.f * e[t]);
    if (blockIdx.x == 0) {
        const float4* row = (const float4*)(e + threadIdx.x * DDIM);
        float s = 0.f;
        #pragma unroll
        for (int q = 0; q < 16; ++q) {
            float4 w = __ldg(row + q);
            s = fmaf(w.x, w.x, s); s = fmaf(w.y, w.y, s);
            s = fmaf(w.z, w.z, s); s = fmaf(w.w, w.w, s);
        }
        __half* spare = ((__half*)g_ef16) + threadIdx.x * 72 + 64;
        spare[0] = __float2half_rn(s);
        spare[1] = __float2half_rn(1.0f);
        #pragma unroll
        for (int j = 2; j < 8; ++j) spare[j] = __float2half_rn(0.f);
    }
}

// ===========================================================================
// Main: fp16 MMA filter with folded (1+eN) bias + packed-index argmin +
// margin + in-CTA exact fallback + fused last-CTA finalize.  2 CTAs/SM.
// ===========================================================================
__global__ __launch_bounds__(NTHR, 2)
void vq_mma_kernel(const float* __restrict__ z, const float* __restrict__ e,
                   float* __restrict__ out, int out_size) {
    extern __shared__ char sm[];
    __half* sZh   = (__half*)(sm + SZ_H);
    float*  sZsqP = (float*)(sm + SZSQP);
    float*  sZsq  = (float*)(sm + SZSQ);
    double* sW    = (double*)(sm + S_WS);
    double* sW2   = (double*)(sm + S_WS2);
    // overlays (post-MMA only)
    unsigned* sBP = (unsigned*)(sm + OV_BP);
    unsigned* sSP = (unsigned*)(sm + OV_SP);
    int*    sHist = (int*)(sm + OV_HIST);
    int*    sRowK = (int*)(sm + OV_ROWK);
    int*    sFbC  = (int*)(sm + OV_FBC);
    int*    sFbR  = (int*)(sm + OV_FBR);
    int*    sFbK2 = (int*)(sm + OV_FBK2);
    float*  sFbS2 = (float*)(sm + OV_FBS2);
    int*    sFbK  = (int*)(sm + OV_FBK);
    float*  sFbSC = (float*)(sm + OV_FBSC);
    int*    sLast = (int*)(sm + OV_LAST);

    const int tid  = threadIdx.x;
    const int lane = tid & 31;
    const int w    = tid >> 5;
    const int p0   = blockIdx.x * 128;
    const int zbase = (p0 >> 12) * 262144 + (p0 & 4095);

    // ---- stage codebook fp16 (wide copy, spare cols carry eN/1.0) ----
    {
        uint4* dEh = (uint4*)(sm + SE_H);
        #pragma unroll
        for (int i = 0; i < 9; ++i) {              // 4608 = 512*9
            int idx = tid + NTHR * i;
            dEh[idx] = g_ef16[idx];
        }
    }
    // ---- stage z: fp16 + zsq partials ----
    {
        const int row  = tid & 127;
        const int part = tid >> 7;
        float s = 0.f;
        #pragma unroll
        for (int j = 0; j < 16; ++j) {
            int d = part * 16 + j;
            float v = __ldg(z + zbase + row + d * 4096);
            s = fmaf(v, v, s);
            sZh[row * 72 + d] = __float2half_rn(v);
        }
        sZsqP[part * 128 + row] = s;
    }
    __syncthreads();
    if (tid < 128)
        sZsq[tid] = ((sZsqP[tid] + sZsqP[128 + tid]) + sZsqP[256 + tid]) + sZsqP[384 + tid];
    __syncthreads();

    // ---- MMA streaming: warp = (m-tile, code-half); 2 n-tiles per iter ----
    const int mtile = w & 7;
    const int nhalf = w >> 3;
    const int m0  = mtile * 16;
    const int g   = lane >> 2;
    const int tig = lane & 3;

    const unsigned smemBase = smem_u32(sm);
    const unsigned aRow = (unsigned)((m0 + ((lane >> 3) & 1) * 8 + (lane & 7)) * 144
                                     + (lane >> 4) * 16);
    const unsigned aAh = smemBase + SZ_H + aRow;
    const int nbase0 = nhalf * 256;
    // B k16 ldmatrix lane addr: tile = bit4, k-half = bit3
    const unsigned bConst = smemBase + SE_H
        + (unsigned)(((lane >> 4) * 8 + (lane & 7)) * 144 + ((lane >> 3) & 1) * 16)
        + (unsigned)nbase0 * 144u;
    // B k8 (bias cols 64-71) ldmatrix.x2 lane addr: matrix = bit3
    const unsigned k8Const = smemBase + SE_H
        + (unsigned)((nbase0 + ((lane >> 3) & 1) * 8 + (lane & 7)) * 144 + 128);
    // A k8 fragment: rows all-ones at local cols 0,1 (global 64,65) -> constant
    const unsigned aK8 = (tig == 0) ? 0x3C003C00u : 0u;

    unsigned Ah[4][4];                  // resident A (16 regs)
    #pragma unroll
    for (int ks = 0; ks < 4; ++ks)
        LDSM4(Ah[ks][0], Ah[ks][1], Ah[ks][2], Ah[ks][3], aAh + ks * 32u);

    unsigned m1r0 = 0xFFFFFFFFu, m2r0 = 0xFFFFFFFFu;
    unsigned m1r1 = 0xFFFFFFFFu, m2r1 = 0xFFFFFFFFu;

    for (int nt2 = 0; nt2 < 16; ++nt2) {
        const int nb = nbase0 + nt2 * 16;
        float c[2][4];
        c[0][0] = c[0][1] = c[0][2] = c[0][3] = 0.f;
        c[1][0] = c[1][1] = c[1][2] = c[1][3] = 0.f;
        // bias step: c += 1.0 + eN  (k8 over spare cols)
        {
            unsigned e0, e1;
            LDSM2(e0, e1, k8Const + (unsigned)(nt2 * 2304));
            mma16808h(c[0][0], c[0][1], c[0][2], c[0][3], aK8, aK8, e0);
            mma16808h(c[1][0], c[1][1], c[1][2], c[1][3], aK8, aK8, e1);
        }
        #pragma unroll
        for (int ks = 0; ks < 4; ++ks) {
            unsigned b0, b1, b2, b3;
            LDSM4(b0, b1, b2, b3, bConst + (unsigned)(nt2 * 2304 + ks * 32));
            mma16816h(c[0][0], c[0][1], c[0][2], c[0][3],
                      Ah[ks][0], Ah[ks][1], Ah[ks][2], Ah[ks][3], b0, b1);   // tile 0
            mma16816h(c[1][0], c[1][1], c[1][2], c[1][3],
                      Ah[ks][0], Ah[ks][1], Ah[ks][2], Ah[ks][3], b2, b3);   // tile 1
        }
        #pragma unroll
        for (int t = 0; t < 2; ++t) {
            const int kA = nb + t * 8 + 2 * tig;
            unsigned p00 = packscore(c[t][0], kA);
            unsigned p01 = packscore(c[t][1], kA + 1);
            unsigned p10 = packscore(c[t][2], kA);
            unsigned p11 = packscore(c[t][3], kA + 1);
            m2r0 = umn(m2r0, umx(m1r0, p00)); m1r0 = umn(m1r0, p00);
            m2r0 = umn(m2r0, umx(m1r0, p01)); m1r0 = umn(m1r0, p01);
            m2r1 = umn(m2r1, umx(m1r1, p10)); m1r1 = umn(m1r1, p10);
            m2r1 = umn(m2r1, umx(m1r1, p11)); m1r1 = umn(m1r1, p11);
        }
    }

    // cross-lane merge within 4-lane groups (packed, order-free)
    #pragma unroll
    for (int d = 1; d <= 2; d <<= 1) {
        unsigned o1 = __shfl_xor_sync(0xffffffffu, m1r0, d);
        unsigned o2 = __shfl_xor_sync(0xffffffffu, m2r0, d);
        m2r0 = umn(umx(m1r0, o1), umn(m2r0, o2));
        m1r0 = umn(m1r0, o1);
        o1 = __shfl_xor_sync(0xffffffffu, m1r1, d);
        o2 = __shfl_xor_sync(0xffffffffu, m2r1, d);
        m2r1 = umn(umx(m1r1, o1), umn(m2r1, o2));
        m1r1 = umn(m1r1, o1);
    }

    // ---- ALL warps done reading E before overlay writes ----
    __syncthreads();
    if (tig == 0) {
        int r0 = m0 + g, r1 = m0 + g + 8;
        sBP[r0 * 2 + nhalf] = m1r0; sSP[r0 * 2 + nhalf] = m2r0;
        sBP[r1 * 2 + nhalf] = m1r1; sSP[r1 * 2 + nhalf] = m2r1;
    }
    sHist[tid] = 0;
    if (tid == 0) *sFbC = 0;
    __syncthreads();

    // ---- per-row merge + margin test -> sRowK ----
    double dacc = 0.0;
    if (tid < 128) {
        unsigned m1a = sBP[tid * 2], m1b = sBP[tid * 2 + 1];
        unsigned m2a = sSP[tid * 2], m2b = sSP[tid * 2 + 1];
        unsigned m1 = umn(m1a, m1b);
        unsigned m2 = umn(umx(m1a, m1b), umn(m2a, m2b));
        float bf = __uint_as_float(m1 & 0xFFFFFE00u);
        float sf = __uint_as_float(m2 & 0xFFFFFE00u);
        int kk = (int)(m1 & 511u);
        if (sf - bf > TAU) {
            atomicAdd(&sHist[kk], 1);
            dacc = (double)(sZsq[tid] + (bf - 1.0f));   // dist = zq + (score - bias)
            sRowK[tid] = kk;
        } else {
            int idx = atomicAdd(sFbC, 1);
            sFbR[idx] = tid;
            sRowK[tid] = -1;
        }
    }
    __syncthreads();

    // ---- z_q scatter: all 512 threads, coalesced ----
    {
        const int r = tid & 127, part = tid >> 7;
        const int kk = sRowK[r];
        if (kk >= 0) {
            const float4* er = (const float4*)(e + kk * DDIM) + part * 4;
            float* o = out + 1 + zbase + r;
            #pragma unroll
            for (int q = 0; q < 4; ++q) {
                float4 v = __ldg(er + q);
                int d0 = part * 16 + 4 * q;
                o[(d0)     * 4096] = v.x;
                o[(d0 + 1) * 4096] = v.y;
                o[(d0 + 2) * 4096] = v.z;
                o[(d0 + 3) * 4096] = v.w;
            }
        }
    }
    __syncthreads();

    // ---- in-CTA exact fp32 fallback (validated R8-R13 code, overlay buffers) ----
    const int nfb = *sFbC;
    double fbacc = 0.0;
    float* fsc = (float*)(sm + OV_FSC);
    float* fzs = (float*)(sm + OV_FZS);
    float* fzq = (float*)(sm + OV_FZQ);
    for (int base = 0; base < nfb; base += 8) {
        const int nb = min(8, nfb - base);
        {
            int r = tid >> 6, d = tid & 63;
            if (r < nb)
                fzs[r * 64 + d] = __ldg(z + zbase + sFbR[base + r] + d * 4096);
        }
        __syncthreads();
        if (tid < nb) {
            float s = 0.f;
            #pragma unroll 8
            for (int d = 0; d < 64; ++d) { float f = fzs[tid * 64 + d]; s = fmaf(f, f, s); }
            fzq[tid] = s;
        }
        __syncthreads();
        {
            float alo[8], ahi[8], blo[8], bhi[8];
            #pragma unroll
            for (int r = 0; r < 8; ++r) { alo[r] = ahi[r] = blo[r] = bhi[r] = 0.f; }
            float s_en = 0.f;
            const float4* er = (const float4*)(e + tid * DDIM);
            #pragma unroll
            for (int q = 0; q < 16; ++q) {
                float4 v = __ldg(er + q);
                s_en = fmaf(v.x, v.x, s_en); s_en = fmaf(v.y, v.y, s_en);
                s_en = fmaf(v.z, v.z, s_en); s_en = fmaf(v.w, v.w, s_en);
                float mx = -2.f * v.x, my = -2.f * v.y, mz = -2.f * v.z, mw = -2.f * v.w;
                #pragma unroll
                for (int r = 0; r < 8; ++r) {
                    float4 zv = *(const float4*)&fzs[r * 64 + 4 * q];
                    alo[r] = fmaf(zv.x, mx, alo[r]);
                    ahi[r] = fmaf(zv.y, my, ahi[r]);
                    blo[r] = fmaf(zv.z, mz, blo[r]);
                    bhi[r] = fmaf(zv.w, mw, bhi[r]);
                }
            }
            #pragma unroll
            for (int r = 0; r < 8; ++r) {
                float s = (alo[r] + blo[r]) + (ahi[r] + bhi[r]);
                fsc[r * 512 + tid] = (fzq[r] + s_en) + s;
            }
        }
        __syncthreads();
        {
            int r = tid >> 6, j = tid & 63;
            float bs = 3.4e38f; int bk = 1 << 30;
            if (r < nb) {
                #pragma unroll
                for (int i = 0; i < 8; ++i) {
                    int k = j + 64 * i;
                    float s = fsc[r * 512 + k];
                    if (s < bs || (s == bs && k < bk)) { bs = s; bk = k; }
                }
            }
            #pragma unroll
            for (int off = 16; off > 0; off >>= 1) {
                float os = __shfl_down_sync(0xffffffffu, bs, off);
                int   ok = __shfl_down_sync(0xffffffffu, bk, off);
                if (os < bs || (os == bs && ok < bk)) { bs = os; bk = ok; }
            }
            if (lane == 0 && r < nb) {
                int half = (tid >> 5) & 1;
                sFbK2[r * 2 + half] = bk;
                sFbS2[r * 2 + half] = bs;
            }
        }
        __syncthreads();
        if (tid < nb) {
            int kk0 = sFbK2[tid * 2], kk1 = sFbK2[tid * 2 + 1];
            float s0 = sFbS2[tid * 2], s1 = sFbS2[tid * 2 + 1];
            bool t1 = (s1 < s0) || (s1 == s0 && kk1 < kk0);
            int kk = t1 ? kk1 : kk0;
            sFbK[tid]  = kk;
            sFbSC[tid] = t1 ? s1 : s0;
            atomicAdd(&sHist[kk], 1);
        }
        __syncthreads();
        if (tid == 0) {
            for (int r = 0; r < nb; ++r) fbacc += (double)sFbSC[r];
        }
        if (tid < 128) {
            int r = tid >> 4, q = tid & 15;
            if (r < nb) {
                int kk = sFbK[r];
                float4 v = __ldg((const float4*)(e + kk * DDIM) + q);
                float* o = out + 1 + zbase + sFbR[base + r];
                o[(4 * q)     * 4096] = v.x;
                o[(4 * q + 1) * 4096] = v.y;
                o[(4 * q + 2) * 4096] = v.z;
                o[(4 * q + 3) * 4096] = v.w;
            }
        }
        __syncthreads();
    }

    // ---- per-CTA reductions out ----
    #pragma unroll
    for (int off = 16; off > 0; off >>= 1)
        dacc += __shfl_down_sync(0xffffffffu, dacc, off);
    if (tid < 128 && lane == 0) sW[w] = dacc;
    __syncthreads();
    if (tid == 0)
        g_sse[blockIdx.x] = ((((sW[0] + sW[1]) + sW[2]) + sW[3])) + fbacc;
    {
        int c = sHist[tid];
        if (c) atomicAdd(&g_counts[tid], c);
    }

    // ---- fused finalize: last CTA does loss + perplexity ----
    __threadfence();
    __syncthreads();
    if (tid == 0) *sLast = (atomicAdd(&g_done, 1u) == GRID - 1u) ? 1 : 0;
    __syncthreads();
    if (*sLast) {
        __threadfence();
        double em = (double)g_counts[tid] * (1.0 / 131072.0);
        g_counts[tid] = 0;
        double x = em + 1e-10;
        double term = x * log(x);
        double ds = g_sse[tid] + g_sse[tid + 512];
        #pragma unroll
        for (int off = 16; off > 0; off >>= 1) {
            term += __shfl_down_sync(0xffffffffu, term, off);
            ds   += __shfl_down_sync(0xffffffffu, ds, off);
        }
        if (lane == 0) { sW[w] = ds; sW2[w] = term; }
        __syncthreads();
        if (tid == 0) {
            double ent = 0.0, sse = 0.0;
            #pragma unroll
            for (int i = 0; i < 16; ++i) { ent += sW2[i]; sse += sW[i]; }
            double mse = sse / 8388608.0;
            out[0]            = (float)(1.25 * mse);
            out[out_size - 1] = (float)exp(-ent);
            g_done = 0;                       // replay-safe reset
        }
    }
}

// ---------------------------------------------------------------------------
extern "C" void kernel_launch(void* const* d_in, const int* in_sizes, int n_in,
                              void* d_out, int out_size) {
    const float* z = (const float*)d_in[0];
    const float* e = (const float*)d_in[1];
    if (n_in >= 2 && in_sizes[0] == KCODES * DDIM && in_sizes[1] == N_POS * DDIM) {
        const float* tmp = z; z = e; e = tmp;      // defensive order swap
    }
    cudaFuncSetAttribute(vq_mma_kernel, cudaFuncAttributeMaxDynamicSharedMemorySize, MAIN_SMEM);

    prep_kernel<<<64, 512>>>(e);
    vq_mma_kernel<<<GRID, NTHR, MAIN_SMEM>>>(z, e, (float*)d_out, out_size);
}

// round 15
// speedup vs baseline: 1.0249x; 1.0249x over previous
#include <cuda_runtime.h>
#include <cuda_fp16.h>
#include <math.h>

#define N_POS   131072
#define KCODES  512
#define DDIM    64
#define GRID    1024             // 128 positions per CTA
#define NTHR    512
#define TAU     2.5e-4f

// ---- device scratch (no allocation allowed) ----
__device__ uint4  g_ef16[4608];    // fp16 of -2e, [k][pitch72 halves]  (73728 B)
__device__ float  g_en1[KCODES];   // 1 + ||e_k||^2
__device__ int    g_counts[KCODES];
__device__ double g_sse[GRID];
__device__ unsigned g_done;        // zero-init; self-resetting

// ---------- helpers ----------
static __device__ __forceinline__ void mma16816h(float& c0, float& c1, float& c2, float& c3,
                                                 unsigned a0, unsigned a1, unsigned a2, unsigned a3,
                                                 unsigned b0, unsigned b1) {
    asm volatile("mma.sync.aligned.m16n8k16.row.col.f32.f16.f16.f32 "
                 "{%0,%1,%2,%3}, {%4,%5,%6,%7}, {%8,%9}, {%0,%1,%2,%3};"
                 : "+f"(c0), "+f"(c1), "+f"(c2), "+f"(c3)
                 : "r"(a0), "r"(a1), "r"(a2), "r"(a3), "r"(b0), "r"(b1));
}
#define LDSM4(d0, d1, d2, d3, addr)                                          \
    asm volatile("ldmatrix.sync.aligned.m8n8.x4.shared.b16 {%0,%1,%2,%3}, [%4];" \
                 : "=r"(d0), "=r"(d1), "=r"(d2), "=r"(d3) : "r"(addr))

static __device__ __forceinline__ unsigned smem_u32(const void* p) {
    unsigned a;
    asm("{ .reg .u64 t; cvta.to.shared.u64 t, %1; cvt.u32.u64 %0, t; }" : "=r"(a) : "l"(p));
    return a;
}
static __device__ __forceinline__ unsigned umn(unsigned a, unsigned b) { return a < b ? a : b; }
static __device__ __forceinline__ unsigned umx(unsigned a, unsigned b) { return a > b ? a : b; }
static __device__ __forceinline__ unsigned packscore(float s, int k) {
    return (__float_as_uint(s) & 0xFFFFFE00u) | (unsigned)k;
}

// ---------- smem layout (bytes), fixed regions: 97024 total ----------
#define SE_H   0                 // e fp16 [512][72] pitch 144B (dead after MMA -> overlay)
#define SZ_H   73728             // z fp16 [128][72]
#define SEN    92160             // float[512] = 1 + eN
#define SZSQP  94208             // float[512]
#define SZSQ   96256             // float[128]
#define S_WS   96768             // double[16]
#define S_WS2  96896             // double[16]
#define MAIN_SMEM 97024
// ---- overlays inside SE_H (valid only AFTER post-MMA syncthreads) ----
#define OV_BP    0               // uint[256] packed best
#define OV_SP    1024            // uint[256] packed sec
#define OV_HIST  2048            // int[512]
#define OV_ROWK  4096            // int[128]
#define OV_FBC   4608            // int
#define OV_FBR   4736            // int[128]
#define OV_FBK2  5248            // int[16]
#define OV_FBS2  5312            // float[16]
#define OV_FBK   5376            // int[8]
#define OV_FBSC  5408            // float[8]
#define OV_LAST  5440            // int
#define OV_FZS   8192            // float[8][64]
#define OV_FZQ   10240           // float[8]
#define OV_FSC   16384           // float[8][512]

// ===========================================================================
// Prep: codebook -> fp16 of -2e at pitch 72 (global) + en1 = 1 + eN
// ===========================================================================
__global__ void prep_kernel(const float* __restrict__ e) {
    int t = blockIdx.x * blockDim.x + threadIdx.x;   // 64 x 512 = 32768
    int k = t >> 6, d = t & 63;
    ((__half*)g_ef16)[k * 72 + d] = __float2half_rn(-2.f * e[t]);
    if (blockIdx.x == 0) {
        const float4* row = (const float4*)(e + threadIdx.x * DDIM);
        float s = 0.f;
        #pragma unroll
        for (int q = 0; q < 16; ++q) {
            float4 w = __ldg(row + q);
            s = fmaf(w.x, w.x, s); s = fmaf(w.y, w.y, s);
            s = fmaf(w.z, w.z, s); s = fmaf(w.w, w.w, s);
        }
        g_en1[threadIdx.x] = 1.0f + s;
    }
}

// ===========================================================================
// Main: single-pass fp16 MMA filter (R13 loop) + packed-index argmin +
// margin + in-CTA exact fallback + fused last-CTA finalize.  2 CTAs/SM.
// ===========================================================================
__global__ __launch_bounds__(NTHR, 2)
void vq_mma_kernel(const float* __restrict__ z, const float* __restrict__ e,
                   float* __restrict__ out, int out_size) {
    extern __shared__ char sm[];
    __half* sZh   = (__half*)(sm + SZ_H);
    float*  sEN   = (float*)(sm + SEN);
    float*  sZsqP = (float*)(sm + SZSQP);
    float*  sZsq  = (float*)(sm + SZSQ);
    double* sW    = (double*)(sm + S_WS);
    double* sW2   = (double*)(sm + S_WS2);
    // overlays (post-MMA only)
    unsigned* sBP = (unsigned*)(sm + OV_BP);
    unsigned* sSP = (unsigned*)(sm + OV_SP);
    int*    sHist = (int*)(sm + OV_HIST);
    int*    sRowK = (int*)(sm + OV_ROWK);
    int*    sFbC  = (int*)(sm + OV_FBC);
    int*    sFbR  = (int*)(sm + OV_FBR);
    int*    sFbK2 = (int*)(sm + OV_FBK2);
    float*  sFbS2 = (float*)(sm + OV_FBS2);
    int*    sFbK  = (int*)(sm + OV_FBK);
    float*  sFbSC = (float*)(sm + OV_FBSC);
    int*    sLast = (int*)(sm + OV_LAST);

    const int tid  = threadIdx.x;
    const int lane = tid & 31;
    const int w    = tid >> 5;
    const int p0   = blockIdx.x * 128;
    const int zbase = (p0 >> 12) * 262144 + (p0 & 4095);

    // ---- stage codebook fp16 (wide copy) + en1 ----
    {
        uint4* dEh = (uint4*)(sm + SE_H);
        #pragma unroll
        for (int i = 0; i < 9; ++i) {              // 4608 = 512*9
            int idx = tid + NTHR * i;
            dEh[idx] = g_ef16[idx];
        }
        sEN[tid] = g_en1[tid];
    }
    // ---- stage z: fp16 + zsq partials ----
    {
        const int row  = tid & 127;
        const int part = tid >> 7;
        float s = 0.f;
        #pragma unroll
        for (int j = 0; j < 16; ++j) {
            int d = part * 16 + j;
            float v = __ldg(z + zbase + row + d * 4096);
            s = fmaf(v, v, s);
            sZh[row * 72 + d] = __float2half_rn(v);
        }
        sZsqP[part * 128 + row] = s;
    }
    __syncthreads();
    if (tid < 128)
        sZsq[tid] = ((sZsqP[tid] + sZsqP[128 + tid]) + sZsqP[256 + tid]) + sZsqP[384 + tid];
    __syncthreads();

    // ---- MMA streaming: warp = (m-tile, code-half); 2 n-tiles per iter ----
    const int mtile = w & 7;
    const int nhalf = w >> 3;
    const int m0  = mtile * 16;
    const int g   = lane >> 2;
    const int tig = lane & 3;

    const unsigned smemBase = smem_u32(sm);
    const unsigned aRow = (unsigned)((m0 + ((lane >> 3) & 1) * 8 + (lane & 7)) * 144
                                     + (lane >> 4) * 16);
    const unsigned aAh = smemBase + SZ_H + aRow;
    const int nbase0 = nhalf * 256;
    const unsigned bConst = smemBase + SE_H
        + (unsigned)(((lane >> 4) * 8 + (lane & 7)) * 144 + ((lane >> 3) & 1) * 16)
        + (unsigned)nbase0 * 144u;

    unsigned Ah[4][4];                  // resident A (16 regs)
    #pragma unroll
    for (int ks = 0; ks < 4; ++ks)
        LDSM4(Ah[ks][0], Ah[ks][1], Ah[ks][2], Ah[ks][3], aAh + ks * 32u);

    unsigned m1r0 = 0xFFFFFFFFu, m2r0 = 0xFFFFFFFFu;
    unsigned m1r1 = 0xFFFFFFFFu, m2r1 = 0xFFFFFFFFu;

    for (int nt2 = 0; nt2 < 16; ++nt2) {
        const int nb = nbase0 + nt2 * 16;
        float c[2][4];
        c[0][0] = c[0][1] = c[0][2] = c[0][3] = 0.f;
        c[1][0] = c[1][1] = c[1][2] = c[1][3] = 0.f;
        #pragma unroll
        for (int ks = 0; ks < 4; ++ks) {
            unsigned b0, b1, b2, b3;
            LDSM4(b0, b1, b2, b3, bConst + (unsigned)(nt2 * 2304 + ks * 32));
            mma16816h(c[0][0], c[0][1], c[0][2], c[0][3],
                      Ah[ks][0], Ah[ks][1], Ah[ks][2], Ah[ks][3], b0, b1);   // tile 0
            mma16816h(c[1][0], c[1][1], c[1][2], c[1][3],
                      Ah[ks][0], Ah[ks][1], Ah[ks][2], Ah[ks][3], b2, b3);   // tile 1
        }
        #pragma unroll
        for (int t = 0; t < 2; ++t) {
            const int kA = nb + t * 8 + 2 * tig;
            const float2 en = *(const float2*)&sEN[kA];
            unsigned p00 = packscore(en.x + c[t][0], kA);
            unsigned p01 = packscore(en.y + c[t][1], kA + 1);
            unsigned p10 = packscore(en.x + c[t][2], kA);
            unsigned p11 = packscore(en.y + c[t][3], kA + 1);
            m2r0 = umn(m2r0, umx(m1r0, p00)); m1r0 = umn(m1r0, p00);
            m2r0 = umn(m2r0, umx(m1r0, p01)); m1r0 = umn(m1r0, p01);
            m2r1 = umn(m2r1, umx(m1r1, p10)); m1r1 = umn(m1r1, p10);
            m2r1 = umn(m2r1, umx(m1r1, p11)); m1r1 = umn(m1r1, p11);
        }
    }

    // cross-lane merge within 4-lane groups (packed, order-free)
    #pragma unroll
    for (int d = 1; d <= 2; d <<= 1) {
        unsigned o1 = __shfl_xor_sync(0xffffffffu, m1r0, d);
        unsigned o2 = __shfl_xor_sync(0xffffffffu, m2r0, d);
        m2r0 = umn(umx(m1r0, o1), umn(m2r0, o2));
        m1r0 = umn(m1r0, o1);
        o1 = __shfl_xor_sync(0xffffffffu, m1r1, d);
        o2 = __shfl_xor_sync(0xffffffffu, m2r1, d);
        m2r1 = umn(umx(m1r1, o1), umn(m2r1, o2));
        m1r1 = umn(m1r1, o1);
    }

    // ---- ALL warps done reading E before overlay writes ----
    __syncthreads();
    if (tig == 0) {
        int r0 = m0 + g, r1 = m0 + g + 8;
        sBP[r0 * 2 + nhalf] = m1r0; sSP[r0 * 2 + nhalf] = m2r0;
        sBP[r1 * 2 + nhalf] = m1r1; sSP[r1 * 2 + nhalf] = m2r1;
    }
    sHist[tid] = 0;
    if (tid == 0) *sFbC = 0;
    __syncthreads();

    // ---- per-row merge + margin test -> sRowK ----
    double dacc = 0.0;
    if (tid < 128) {
        unsigned m1a = sBP[tid * 2], m1b = sBP[tid * 2 + 1];
        unsigned m2a = sSP[tid * 2], m2b = sSP[tid * 2 + 1];
        unsigned m1 = umn(m1a, m1b);
        unsigned m2 = umn(umx(m1a, m1b), umn(m2a, m2b));
        float bf = __uint_as_float(m1 & 0xFFFFFE00u);
        float sf = __uint_as_float(m2 & 0xFFFFFE00u);
        int kk = (int)(m1 & 511u);
        if (sf - bf > TAU) {
            atomicAdd(&sHist[kk], 1);
            dacc = (double)(sZsq[tid] + (bf - 1.0f));   // dist = zq + (score - 1)
            sRowK[tid] = kk;
        } else {
            int idx = atomicAdd(sFbC, 1);
            sFbR[idx] = tid;
            sRowK[tid] = -1;
        }
    }
    __syncthreads();

    // ---- z_q scatter: all 512 threads, coalesced ----
    {
        const int r = tid & 127, part = tid >> 7;
        const int kk = sRowK[r];
        if (kk >= 0) {
            const float4* er = (const float4*)(e + kk * DDIM) + part * 4;
            float* o = out + 1 + zbase + r;
            #pragma unroll
            for (int q = 0; q < 4; ++q) {
                float4 v = __ldg(er + q);
                int d0 = part * 16 + 4 * q;
                o[(d0)     * 4096] = v.x;
                o[(d0 + 1) * 4096] = v.y;
                o[(d0 + 2) * 4096] = v.z;
                o[(d0 + 3) * 4096] = v.w;
            }
        }
    }
    __syncthreads();

    // ---- in-CTA exact fp32 fallback (validated R8-R13 code, overlay buffers) ----
    const int nfb = *sFbC;
    double fbacc = 0.0;
    float* fsc = (float*)(sm + OV_FSC);
    float* fzs = (float*)(sm + OV_FZS);
    float* fzq = (float*)(sm + OV_FZQ);
    for (int base = 0; base < nfb; base += 8) {
        const int nb = min(8, nfb - base);
        {
            int r = tid >> 6, d = tid & 63;
            if (r < nb)
                fzs[r * 64 + d] = __ldg(z + zbase + sFbR[base + r] + d * 4096);
        }
        __syncthreads();
        if (tid < nb) {
            float s = 0.f;
            #pragma unroll 8
            for (int d = 0; d < 64; ++d) { float f = fzs[tid * 64 + d]; s = fmaf(f, f, s); }
            fzq[tid] = s;
        }
        __syncthreads();
        {
            float alo[8], ahi[8], blo[8], bhi[8];
            #pragma unroll
            for (int r = 0; r < 8; ++r) { alo[r] = ahi[r] = blo[r] = bhi[r] = 0.f; }
            float s_en = 0.f;
            const float4* er = (const float4*)(e + tid * DDIM);
            #pragma unroll
            for (int q = 0; q < 16; ++q) {
                float4 v = __ldg(er + q);
                s_en = fmaf(v.x, v.x, s_en); s_en = fmaf(v.y, v.y, s_en);
                s_en = fmaf(v.z, v.z, s_en); s_en = fmaf(v.w, v.w, s_en);
                float mx = -2.f * v.x, my = -2.f * v.y, mz = -2.f * v.z, mw = -2.f * v.w;
                #pragma unroll
                for (int r = 0; r < 8; ++r) {
                    float4 zv = *(const float4*)&fzs[r * 64 + 4 * q];
                    alo[r] = fmaf(zv.x, mx, alo[r]);
                    ahi[r] = fmaf(zv.y, my, ahi[r]);
                    blo[r] = fmaf(zv.z, mz, blo[r]);
                    bhi[r] = fmaf(zv.w, mw, bhi[r]);
                }
            }
            #pragma unroll
            for (int r = 0; r < 8; ++r) {
                float s = (alo[r] + blo[r]) + (ahi[r] + bhi[r]);
                fsc[r * 512 + tid] = (fzq[r] + s_en) + s;
            }
        }
        __syncthreads();
        {
            int r = tid >> 6, j = tid & 63;
            float bs = 3.4e38f; int bk = 1 << 30;
            if (r < nb) {
                #pragma unroll
                for (int i = 0; i < 8; ++i) {
                    int k = j + 64 * i;
                    float s = fsc[r * 512 + k];
                    if (s < bs || (s == bs && k < bk)) { bs = s; bk = k; }
                }
            }
            #pragma unroll
            for (int off = 16; off > 0; off >>= 1) {
                float os = __shfl_down_sync(0xffffffffu, bs, off);
                int   ok = __shfl_down_sync(0xffffffffu, bk, off);
                if (os < bs || (os == bs && ok < bk)) { bs = os; bk = ok; }
            }
            if (lane == 0 && r < nb) {
                int half = (tid >> 5) & 1;
                sFbK2[r * 2 + half] = bk;
                sFbS2[r * 2 + half] = bs;
            }
        }
        __syncthreads();
        if (tid < nb) {
            int kk0 = sFbK2[tid * 2], kk1 = sFbK2[tid * 2 + 1];
            float s0 = sFbS2[tid * 2], s1 = sFbS2[tid * 2 + 1];
            bool t1 = (s1 < s0) || (s1 == s0 && kk1 < kk0);
            int kk = t1 ? kk1 : kk0;
            sFbK[tid]  = kk;
            sFbSC[tid] = t1 ? s1 : s0;
            atomicAdd(&sHist[kk], 1);
        }
        __syncthreads();
        if (tid == 0) {
            for (int r = 0; r < nb; ++r) fbacc += (double)sFbSC[r];
        }
        if (tid < 128) {
            int r = tid >> 4, q = tid & 15;
            if (r < nb) {
                int kk = sFbK[r];
                float4 v = __ldg((const float4*)(e + kk * DDIM) + q);
                float* o = out + 1 + zbase + sFbR[base + r];
                o[(4 * q)     * 4096] = v.x;
                o[(4 * q + 1) * 4096] = v.y;
                o[(4 * q + 2) * 4096] = v.z;
                o[(4 * q + 3) * 4096] = v.w;
            }
        }
        __syncthreads();
    }

    // ---- per-CTA reductions out ----
    #pragma unroll
    for (int off = 16; off > 0; off >>= 1)
        dacc += __shfl_down_sync(0xffffffffu, dacc, off);
    if (tid < 128 && lane == 0) sW[w] = dacc;
    __syncthreads();
    if (tid == 0)
        g_sse[blockIdx.x] = ((((sW[0] + sW[1]) + sW[2]) + sW[3])) + fbacc;
    {
        int c = sHist[tid];
        if (c) atomicAdd(&g_counts[tid], c);
    }

    // ---- fused finalize: last CTA does loss + perplexity ----
    __threadfence();
    __syncthreads();
    if (tid == 0) *sLast = (atomicAdd(&g_done, 1u) == GRID - 1u) ? 1 : 0;
    __syncthreads();
    if (*sLast) {
        __threadfence();
        double em = (double)g_counts[tid] * (1.0 / 131072.0);
        g_counts[tid] = 0;
        double x = em + 1e-10;
        double term = x * log(x);
        double ds = g_sse[tid] + g_sse[tid + 512];
        #pragma unroll
        for (int off = 16; off > 0; off >>= 1) {
            term += __shfl_down_sync(0xffffffffu, term, off);
            ds   += __shfl_down_sync(0xffffffffu, ds, off);
        }
        if (lane == 0) { sW[w] = ds; sW2[w] = term; }
        __syncthreads();
        if (tid == 0) {
            double ent = 0.0, sse = 0.0;
            #pragma unroll
            for (int i = 0; i < 16; ++i) { ent += sW2[i]; sse += sW[i]; }
            double mse = sse / 8388608.0;
            out[0]            = (float)(1.25 * mse);
            out[out_size - 1] = (float)exp(-ent);
            g_done = 0;                       // replay-safe reset
        }
    }
}

// ---------------------------------------------------------------------------
extern "C" void kernel_launch(void* const* d_in, const int* in_sizes, int n_in,
                              void* d_out, int out_size) {
    const float* z = (const float*)d_in[0];
    const float* e = (const float*)d_in[1];
    if (n_in >= 2 && in_sizes[0] == KCODES * DDIM && in_sizes[1] == N_POS * DDIM) {
        const float* tmp = z; z = e; e = tmp;      // defensive order swap
    }
    cudaFuncSetAttribute(vq_mma_kernel, cudaFuncAttributeMaxDynamicSharedMemorySize, MAIN_SMEM);

    prep_kernel<<<64, 512>>>(e);
    vq_mma_kernel<<<GRID, NTHR, MAIN_SMEM>>>(z, e, (float*)d_out, out_size);
}